// round 15
// baseline (speedup 1.0000x reference)
#include <cuda_runtime.h>
#include <cuda_bf16.h>
#include <math.h>
#include <stdint.h>

// Problem constants
#define LNUM 8
#define DDIM 1024
#define HNUM 16
#define DKDIM 64
#define FDIM 4096
#define VDIM 32000
#define SDIM 1024
#define BNUM 2
#define MROWS (BNUM * SDIM)   // 2048

// ---------------- scratch (device globals; no runtime allocation) ----------
__device__ float g_x[MROWS * DDIM];
__device__ __nv_bfloat16 g_hh  [MROWS * DDIM];
__device__ __nv_bfloat16 g_hl  [MROWS * DDIM];
__device__ __nv_bfloat16 g_qkvh[3 * MROWS * DDIM];
__device__ __nv_bfloat16 g_qkvl[3 * MROWS * DDIM];
__device__ __nv_bfloat16 g_atth[MROWS * DDIM];
__device__ __nv_bfloat16 g_attl[MROWS * DDIM];
__device__ __nv_bfloat16 g_midh[MROWS * FDIM];
__device__ __nv_bfloat16 g_midl[MROWS * FDIM];
__device__ __nv_bfloat16 g_wqkvh[3 * LNUM * DDIM * DDIM];
__device__ __nv_bfloat16 g_wqkvl[3 * LNUM * DDIM * DDIM];
__device__ __nv_bfloat16 g_woh[LNUM * DDIM * DDIM];
__device__ __nv_bfloat16 g_wol[LNUM * DDIM * DDIM];
__device__ __nv_bfloat16 g_w1h[LNUM * DDIM * FDIM];
__device__ __nv_bfloat16 g_w1l[LNUM * DDIM * FDIM];
__device__ __nv_bfloat16 g_w2h[LNUM * DDIM * FDIM];
__device__ __nv_bfloat16 g_w2l[LNUM * DDIM * FDIM];
__device__ __nv_bfloat16 g_wouth[DDIM * VDIM];
__device__ __nv_bfloat16 g_woutl[DDIM * VDIM];

// ======================= PTX helpers (portable, sm_80+) =====================
__device__ __forceinline__ uint32_t smem_u32(const void* p) {
    uint32_t a;
    asm("{ .reg .u64 t; cvta.to.shared.u64 t, %1; cvt.u32.u64 %0, t; }"
        : "=r"(a) : "l"(p));
    return a;
}
__device__ __forceinline__ void ldsm4(uint32_t* r, uint32_t addr) {
    asm volatile("ldmatrix.sync.aligned.m8n8.x4.shared.b16 {%0,%1,%2,%3}, [%4];"
        : "=r"(r[0]), "=r"(r[1]), "=r"(r[2]), "=r"(r[3]) : "r"(addr));
}
__device__ __forceinline__ void ldsm4t(uint32_t* r, uint32_t addr) {
    asm volatile("ldmatrix.sync.aligned.m8n8.x4.trans.shared.b16 {%0,%1,%2,%3}, [%4];"
        : "=r"(r[0]), "=r"(r[1]), "=r"(r[2]), "=r"(r[3]) : "r"(addr));
}
__device__ __forceinline__ void mma16816(float* c, const uint32_t* a,
                                         const uint32_t* b) {
    asm volatile(
        "mma.sync.aligned.m16n8k16.row.col.f32.bf16.bf16.f32 "
        "{%0,%1,%2,%3}, {%4,%5,%6,%7}, {%8,%9}, {%0,%1,%2,%3};"
        : "+f"(c[0]), "+f"(c[1]), "+f"(c[2]), "+f"(c[3])
        : "r"(a[0]), "r"(a[1]), "r"(a[2]), "r"(a[3]), "r"(b[0]), "r"(b[1]));
}
__device__ __forceinline__ void mma2(float* c, const uint32_t* a,
                                     uint32_t b0, uint32_t b1) {
    asm volatile(
        "mma.sync.aligned.m16n8k16.row.col.f32.bf16.bf16.f32 "
        "{%0,%1,%2,%3}, {%4,%5,%6,%7}, {%8,%9}, {%0,%1,%2,%3};"
        : "+f"(c[0]), "+f"(c[1]), "+f"(c[2]), "+f"(c[3])
        : "r"(a[0]), "r"(a[1]), "r"(a[2]), "r"(a[3]), "r"(b0), "r"(b1));
}
__device__ __forceinline__ void cpa16(uint32_t d, const void* s) {
    asm volatile("cp.async.cg.shared.global [%0], [%1], 16;" :: "r"(d), "l"(s));
}
#define CP_COMMIT() asm volatile("cp.async.commit_group;" ::: "memory")
#define CP_WAIT1()  asm volatile("cp.async.wait_group 1;" ::: "memory")

__device__ __forceinline__ uint32_t packbf2(__nv_bfloat16 a, __nv_bfloat16 b) {
    __nv_bfloat162 t;
    t.x = a; t.y = b;
    return *reinterpret_cast<uint32_t*>(&t);
}
// pack 2 fp32 into bf16x2 hi word + lo (residual) word
__device__ __forceinline__ void split2(float x, float y, uint32_t& h, uint32_t& l) {
    __nv_bfloat16 hx = __float2bfloat16(x);
    __nv_bfloat16 hy = __float2bfloat16(y);
    h = packbf2(hx, hy);
    l = packbf2(__float2bfloat16(x - __bfloat162float(hx)),
                __float2bfloat16(y - __bfloat162float(hy)));
}
__device__ __forceinline__ void cvt_split4(float4 v, uint32_t& h01, uint32_t& h23,
                                           uint32_t& l01, uint32_t& l23) {
    split2(v.x, v.y, h01, l01);
    split2(v.z, v.w, h23, l23);
}

// ---------------- fused split kernel: all 7 weight tensors in one launch ----
__global__ void split_all_kernel(
    const float4* s0, uint2* h0, uint2* l0, int n0,
    const float4* s1, uint2* h1, uint2* l1, int n1,
    const float4* s2, uint2* h2, uint2* l2, int n2,
    const float4* s3, uint2* h3, uint2* l3, int n3,
    const float4* s4, uint2* h4, uint2* l4, int n4,
    const float4* s5, uint2* h5, uint2* l5, int n5,
    const float4* s6, uint2* h6, uint2* l6, int n6)
{
    const float4* src; uint2* hi; uint2* lo; int n;
    switch (blockIdx.y) {
        case 0: src = s0; hi = h0; lo = l0; n = n0; break;
        case 1: src = s1; hi = h1; lo = l1; n = n1; break;
        case 2: src = s2; hi = h2; lo = l2; n = n2; break;
        case 3: src = s3; hi = h3; lo = l3; n = n3; break;
        case 4: src = s4; hi = h4; lo = l4; n = n4; break;
        case 5: src = s5; hi = h5; lo = l5; n = n5; break;
        default: src = s6; hi = h6; lo = l6; n = n6; break;
    }
    int i = blockIdx.x * blockDim.x + threadIdx.x;
    int stride = gridDim.x * blockDim.x;
    for (; i < n; i += stride) {
        float4 v = src[i];
        uint32_t a01, a23, b01, b23;
        cvt_split4(v, a01, a23, b01, b23);
        hi[i] = make_uint2(a01, a23);
        lo[i] = make_uint2(b01, b23);
    }
}

// ---------------- async-pipelined tensor-core GEMM --------------------------
// CTA 128x128x64, 8 warps (2x4), warp tile 64x32, 2-stage ring, BK=64.
// A smem row: 64 elems + 8 pad = 72 elems (144B = 9*16B, ldmatrix conflict-free)
// B smem row: 128 elems + 8 pad = 136 elems (272B = 17*16B)
#define BM 128
#define BN 128
#define BK 64
#define A_STG 18432            // 128 * 144
#define B_STG 17408            // 64 * 272
#define ALO_OFF (2 * A_STG)    // 36864
#define BHI_OFF (2 * ALO_OFF)  // 73728
#define BLO_OFF (BHI_OFF + 2 * B_STG) // 108544
#define SMEM_MM (BLO_OFF + 2 * B_STG) // 143360 bytes

struct Frag {
    uint32_t ah[4][4];
    uint32_t al[4][4];
    uint32_t bh[2][4];
    uint32_t bl[2][4];
};

template<bool RELU, bool RES, bool OBF>
__global__ void __launch_bounds__(256, 1)
gemm_as(const __nv_bfloat16* __restrict__ Ah, const __nv_bfloat16* __restrict__ Al,
        const __nv_bfloat16* __restrict__ Bh0, const __nv_bfloat16* __restrict__ Bl0,
        size_t wz,
        const float* __restrict__ bias0, const float* __restrict__ bias1,
        const float* __restrict__ bias2,
        float* __restrict__ C0, size_t cz,
        __nv_bfloat16* __restrict__ Ch0, __nv_bfloat16* __restrict__ Cl0,
        int M, int N, int K)
{
    extern __shared__ char smem[];
    uint32_t sb = smem_u32(smem);

    int tid  = threadIdx.x;
    int wid  = tid >> 5;
    int lane = tid & 31;
    int z    = blockIdx.z;
    int bn = blockIdx.x * BN;
    int bm = blockIdx.y * BM;
    int wm = (wid >> 2) * 64;
    int wn = (wid & 3) * 32;

    const __nv_bfloat16* Bh = Bh0 + (size_t)z * wz;
    const __nv_bfloat16* Bl = Bl0 + (size_t)z * wz;
    const float* bias = (z == 0) ? bias0 : (z == 1) ? bias1 : bias2;

    // cp.async sources: A row = tid>>1, 64B chunk; B row = tid>>2, 64B chunk
    const __nv_bfloat16* aH = Ah + (size_t)(bm + (tid >> 1)) * K + (tid & 1) * 32;
    const __nv_bfloat16* aL = Al + (size_t)(bm + (tid >> 1)) * K + (tid & 1) * 32;
    const __nv_bfloat16* bH = Bh + (size_t)(tid >> 2) * N + bn + (tid & 3) * 32;
    const __nv_bfloat16* bL = Bl + (size_t)(tid >> 2) * N + bn + (tid & 3) * 32;
    uint32_t adst = sb + (uint32_t)((tid >> 1) * 144 + (tid & 1) * 64);
    uint32_t bdst = sb + BHI_OFF + (uint32_t)((tid >> 2) * 272 + (tid & 3) * 64);

    const int nst = K / BK;

#define LOADS(s)                                                              \
    {                                                                         \
        if ((s) < nst) {                                                      \
            int buf_ = (s) & 1;                                               \
            uint32_t ad = adst + buf_ * A_STG;                                \
            const __nv_bfloat16* a1 = aH + (s) * BK;                          \
            const __nv_bfloat16* a2 = aL + (s) * BK;                          \
            cpa16(ad,      a1);      cpa16(ad + 16, a1 + 8);                  \
            cpa16(ad + 32, a1 + 16); cpa16(ad + 48, a1 + 24);                 \
            uint32_t al_ = ad + ALO_OFF;                                      \
            cpa16(al_,      a2);      cpa16(al_ + 16, a2 + 8);                \
            cpa16(al_ + 32, a2 + 16); cpa16(al_ + 48, a2 + 24);               \
            uint32_t bd = bdst + buf_ * B_STG;                                \
            const __nv_bfloat16* b1 = bH + (size_t)(s) * BK * N;              \
            const __nv_bfloat16* b2 = bL + (size_t)(s) * BK * N;              \
            cpa16(bd,      b1);      cpa16(bd + 16, b1 + 8);                  \
            cpa16(bd + 32, b1 + 16); cpa16(bd + 48, b1 + 24);                 \
            uint32_t bl_ = bd + (BLO_OFF - BHI_OFF);                          \
            cpa16(bl_,      b2);      cpa16(bl_ + 16, b2 + 8);                \
            cpa16(bl_ + 32, b2 + 16); cpa16(bl_ + 48, b2 + 24);               \
        }                                                                     \
        CP_COMMIT();                                                          \
    }

    int fr_arow = wm + (lane & 15);
    int fr_acol = (lane >> 4) * 8;
    int fr_krow = (lane & 15);
    int fr_ncol = wn + (lane >> 4) * 8;

#define LDFRAG(f, buf, kk)                                                    \
    {                                                                         \
        uint32_t ab_ = sb + (buf) * A_STG;                                    \
        int kc_ = (kk) * 16 + fr_acol;                                        \
        _Pragma("unroll")                                                     \
        for (int mt = 0; mt < 4; mt++) {                                      \
            uint32_t eo = (uint32_t)((fr_arow + mt * 16) * 72 + kc_) * 2;     \
            ldsm4((f).ah[mt], ab_ + eo);                                      \
            ldsm4((f).al[mt], ab_ + ALO_OFF + eo);                            \
        }                                                                     \
        uint32_t bb_ = sb + BHI_OFF + (buf) * B_STG;                          \
        int kr_ = (kk) * 16 + fr_krow;                                        \
        _Pragma("unroll")                                                     \
        for (int nt2 = 0; nt2 < 2; nt2++) {                                   \
            uint32_t eo = (uint32_t)(kr_ * 136 + fr_ncol + nt2 * 16) * 2;     \
            ldsm4t((f).bh[nt2], bb_ + eo);                                    \
            ldsm4t((f).bl[nt2], bb_ + (BLO_OFF - BHI_OFF) + eo);              \
        }                                                                     \
    }

#define DOMMA(f)                                                              \
    {                                                                         \
        _Pragma("unroll")                                                     \
        for (int mt = 0; mt < 4; mt++)                                        \
            _Pragma("unroll")                                                 \
            for (int nt = 0; nt < 4; nt++) {                                  \
                const uint32_t* bhp = &(f).bh[nt >> 1][(nt & 1) * 2];         \
                const uint32_t* blp = &(f).bl[nt >> 1][(nt & 1) * 2];         \
                mma16816(acc[mt][nt], (f).ah[mt], bhp);                       \
                mma16816(acc[mt][nt], (f).ah[mt], blp);                       \
                mma16816(acc[mt][nt], (f).al[mt], bhp);                       \
            }                                                                 \
    }

    float acc[4][4][4];
    #pragma unroll
    for (int i = 0; i < 4; i++)
        #pragma unroll
        for (int j = 0; j < 4; j++)
            #pragma unroll
            for (int r = 0; r < 4; r++) acc[i][j][r] = 0.f;

    Frag fr0, fr1;

    LOADS(0); LOADS(1);
    CP_WAIT1();
    __syncthreads();
    LDFRAG(fr0, 0, 0);

    for (int s = 0; s < nst; s++) {
        int buf = s & 1;
        // 4 half-stages (kk = 0..3), fragment ping-pong one half ahead
        LDFRAG(fr1, buf, 1);
        DOMMA(fr0);
        LDFRAG(fr0, buf, 2);
        DOMMA(fr1);
        LDFRAG(fr1, buf, 3);
        DOMMA(fr0);
        __syncthreads();            // all warps done reading buf before refill
        LOADS(s + 2);               // refill this buffer for stage s+2
        CP_WAIT1();                 // stage s+1's data resident
        if (s + 1 < nst) LDFRAG(fr0, buf ^ 1, 0);
        DOMMA(fr1);
    }

    // ---- epilogue ----
    #pragma unroll
    for (int mt = 0; mt < 4; mt++) {
        int grow = bm + wm + mt * 16 + (lane >> 2);
        #pragma unroll
        for (int nt = 0; nt < 4; nt++) {
            int gcol = bn + wn + nt * 8 + (lane & 3) * 2;
            float2 bb = *(const float2*)(bias + gcol);
            float v0 = acc[mt][nt][0] + bb.x;
            float v1 = acc[mt][nt][1] + bb.y;
            float v2 = acc[mt][nt][2] + bb.x;
            float v3 = acc[mt][nt][3] + bb.y;
            if (RELU) {
                v0 = fmaxf(v0, 0.f); v1 = fmaxf(v1, 0.f);
                v2 = fmaxf(v2, 0.f); v3 = fmaxf(v3, 0.f);
            }
            if (OBF) {
                __nv_bfloat16* Ch = Ch0 + (size_t)z * cz;
                __nv_bfloat16* Cl = Cl0 + (size_t)z * cz;
                size_t o0 = (size_t)grow * N + gcol;
                size_t o1 = (size_t)(grow + 8) * N + gcol;
                uint32_t h0, l0, h1, l1;
                split2(v0, v1, h0, l0);
                split2(v2, v3, h1, l1);
                *(uint32_t*)(Ch + o0) = h0;
                *(uint32_t*)(Cl + o0) = l0;
                *(uint32_t*)(Ch + o1) = h1;
                *(uint32_t*)(Cl + o1) = l1;
            } else {
                float* C = C0 + (size_t)z * cz;
                float* c0 = C + (size_t)grow * N;
                float* c1 = C + (size_t)(grow + 8) * N;
                if (RES) {
                    float2 o0 = *(const float2*)(c0 + gcol);
                    float2 o1 = *(const float2*)(c1 + gcol);
                    v0 += o0.x; v1 += o0.y; v2 += o1.x; v3 += o1.y;
                }
                *(float2*)(c0 + gcol) = make_float2(v0, v1);
                *(float2*)(c1 + gcol) = make_float2(v2, v3);
            }
        }
    }
#undef LOADS
#undef LDFRAG
#undef DOMMA
}

// ---------------- embedding -------------------------------------------------
__global__ void embed_kernel(const int* __restrict__ ids,
                             const float* __restrict__ tok,
                             const float* __restrict__ pos,
                             float* __restrict__ x)
{
    int row = blockIdx.x;
    int s   = row % SDIM;
    int id  = ids[row];
    int tid = threadIdx.x;
    const float* tr = tok + (size_t)id * DDIM;
    const float* pr = pos + (size_t)s  * DDIM;
    float* xr = x + (size_t)row * DDIM;
    #pragma unroll
    for (int i = 0; i < 4; i++) {
        int c = tid + i * 256;
        xr[c] = tr[c] + pr[c];
    }
}

// ---------------- layernorm: warp per row, shfl reductions ------------------
__global__ void ln_kernel(const float* __restrict__ x,
                          const float* __restrict__ g,
                          const float* __restrict__ b,
                          __nv_bfloat16* __restrict__ oh,
                          __nv_bfloat16* __restrict__ ol)
{
    int wid  = threadIdx.x >> 5;
    int lane = threadIdx.x & 31;
    int row  = blockIdx.x * 8 + wid;

    const float4* xr = (const float4*)(x + (size_t)row * DDIM);
    float4 v[8];
    float s = 0.f;
    #pragma unroll
    for (int i = 0; i < 8; i++) {
        v[i] = xr[lane + 32 * i];
        s += v[i].x + v[i].y + v[i].z + v[i].w;
    }
    #pragma unroll
    for (int o = 16; o > 0; o >>= 1) s += __shfl_xor_sync(0xFFFFFFFF, s, o);
    float mean = s * (1.0f / DDIM);

    float vs = 0.f;
    #pragma unroll
    for (int i = 0; i < 8; i++) {
        float dx = v[i].x - mean, dy = v[i].y - mean;
        float dz = v[i].z - mean, dw = v[i].w - mean;
        vs += dx * dx + dy * dy + dz * dz + dw * dw;
    }
    #pragma unroll
    for (int o = 16; o > 0; o >>= 1) vs += __shfl_xor_sync(0xFFFFFFFF, vs, o);
    float inv = rsqrtf(vs * (1.0f / DDIM) + 1e-5f);

    uint2* ohp = (uint2*)(oh + (size_t)row * DDIM);
    uint2* olp = (uint2*)(ol + (size_t)row * DDIM);
    const float4* gp = (const float4*)g;
    const float4* bp = (const float4*)b;
    #pragma unroll
    for (int i = 0; i < 8; i++) {
        int c4 = lane + 32 * i;
        float4 gg = gp[c4];
        float4 bb = bp[c4];
        float4 o4;
        o4.x = (v[i].x - mean) * inv * gg.x + bb.x;
        o4.y = (v[i].y - mean) * inv * gg.y + bb.y;
        o4.z = (v[i].z - mean) * inv * gg.z + bb.z;
        o4.w = (v[i].w - mean) * inv * gg.w + bb.w;
        uint32_t h01, h23, l01, l23;
        cvt_split4(o4, h01, h23, l01, l23);
        ohp[c4] = make_uint2(h01, h23);
        olp[c4] = make_uint2(l01, l23);
    }
}

// ---------------- tensor-core flash attention --------------------------------
#define TQ 128
#define TKT 64
#define ATSTR 144
#define AT_QH 0u
#define AT_QL (TQ * ATSTR)
#define AT_KH (2u * TQ * ATSTR)
#define AT_TILE (TKT * ATSTR)
#define AT_KL (AT_KH + 2 * AT_TILE)
#define AT_VH (AT_KL + 2 * AT_TILE)
#define AT_VL (AT_VH + 2 * AT_TILE)
#define AT_SMEM (AT_VL + 2 * AT_TILE)  // 110592 bytes

__global__ void __launch_bounds__(256, 1)
attn_mma(const __nv_bfloat16* __restrict__ qh, const __nv_bfloat16* __restrict__ ql,
         const __nv_bfloat16* __restrict__ kh, const __nv_bfloat16* __restrict__ kl,
         const __nv_bfloat16* __restrict__ vh, const __nv_bfloat16* __restrict__ vl,
         __nv_bfloat16* __restrict__ oh, __nv_bfloat16* __restrict__ ol)
{
    extern __shared__ char smem[];
    uint32_t sb = smem_u32(smem);
    int tid = threadIdx.x, wid = tid >> 5, lane = tid & 31;
    int qt = gridDim.x - 1 - blockIdx.x;
    int hhd = blockIdx.y, bb = blockIdx.z;
    int hcol = hhd * DKDIM;
    size_t rowbase = (size_t)bb * SDIM;
    int q0 = qt * TQ;

    {
        int r = tid >> 1, hf = (tid & 1) * 32;
        const __nv_bfloat16* s1 = qh + (rowbase + q0 + r) * DDIM + hcol + hf;
        const __nv_bfloat16* s2 = ql + (rowbase + q0 + r) * DDIM + hcol + hf;
        uint32_t d = sb + AT_QH + (uint32_t)(r * ATSTR + hf * 2);
        cpa16(d, s1); cpa16(d + 16, s1 + 8);
        cpa16(d + 32, s1 + 16); cpa16(d + 48, s1 + 24);
        d += AT_QL;
        cpa16(d, s2); cpa16(d + 16, s2 + 8);
        cpa16(d + 32, s2 + 16); cpa16(d + 48, s2 + 24);
    }
    int lr = tid >> 2;
    int lq = (tid & 3) * 16;
#define LOADT(kt_, buf_)                                                      \
    {                                                                         \
        size_t so = (rowbase + (kt_) * TKT + lr) * DDIM + hcol + lq;          \
        uint32_t dd = (uint32_t)(lr * ATSTR + lq * 2);                        \
        uint32_t db = sb + (buf_) * AT_TILE + dd;                             \
        cpa16(db + AT_KH, kh + so); cpa16(db + AT_KH + 16, kh + so + 8);      \
        cpa16(db + AT_KL, kl + so); cpa16(db + AT_KL + 16, kl + so + 8);      \
        cpa16(db + AT_VH, vh + so); cpa16(db + AT_VH + 16, vh + so + 8);      \
        cpa16(db + AT_VL, vl + so); cpa16(db + AT_VL + 16, vl + so + 8);      \
    }
    LOADT(0, 0);
    CP_COMMIT();

    const int ktmax = 2 * qt + 1;
    float m0 = -1e30f, m1 = -1e30f, l0 = 0.f, l1 = 0.f;
    float acc_o[8][4];
    #pragma unroll
    for (int i = 0; i < 8; i++)
        #pragma unroll
        for (int j = 0; j < 4; j++) acc_o[i][j] = 0.f;

    int fr_row = wid * 16 + (lane & 15);
    int fr_col8 = (lane >> 4) * 8;
    int r0g = q0 + wid * 16 + (lane >> 2);
    int r1g = r0g + 8;

    for (int kt = 0; kt <= ktmax; kt++) {
        int buf = kt & 1;
        if (kt < ktmax) LOADT(kt + 1, buf ^ 1);
        CP_COMMIT();
        CP_WAIT1();
        __syncthreads();

        float s[8][4];
        #pragma unroll
        for (int i = 0; i < 8; i++)
            #pragma unroll
            for (int j = 0; j < 4; j++) s[i][j] = 0.f;

        #pragma unroll
        for (int ks = 0; ks < 4; ks++) {
            uint32_t qfh[4], qfl[4];
            uint32_t qeo = (uint32_t)(fr_row * ATSTR + (ks * 16 + fr_col8) * 2);
            ldsm4(qfh, sb + AT_QH + qeo);
            ldsm4(qfl, sb + AT_QL + qeo);
            #pragma unroll
            for (int nt = 0; nt < 4; nt++) {
                uint32_t kfh[4], kfl[4];
                uint32_t keo = (uint32_t)((nt * 16 + (lane & 15)) * ATSTR
                                          + (ks * 16 + fr_col8) * 2);
                ldsm4(kfh, sb + AT_KH + buf * AT_TILE + keo);
                ldsm4(kfl, sb + AT_KL + buf * AT_TILE + keo);
                mma2(s[nt * 2],     qfh, kfh[0], kfh[2]);
                mma2(s[nt * 2],     qfh, kfl[0], kfl[2]);
                mma2(s[nt * 2],     qfl, kfh[0], kfh[2]);
                mma2(s[nt * 2 + 1], qfh, kfh[1], kfh[3]);
                mma2(s[nt * 2 + 1], qfh, kfl[1], kfl[3]);
                mma2(s[nt * 2 + 1], qfl, kfh[1], kfh[3]);
            }
        }

        const float sc = 0.125f;
        bool msk = (kt >= 2 * qt);
        #pragma unroll
        for (int n8 = 0; n8 < 8; n8++) {
            int kc = kt * TKT + n8 * 8 + (lane & 3) * 2;
            s[n8][0] *= sc; s[n8][1] *= sc; s[n8][2] *= sc; s[n8][3] *= sc;
            if (msk) {
                if (kc     > r0g) s[n8][0] = -1e30f;
                if (kc + 1 > r0g) s[n8][1] = -1e30f;
                if (kc     > r1g) s[n8][2] = -1e30f;
                if (kc + 1 > r1g) s[n8][3] = -1e30f;
            }
        }

        float tm0 = -1e30f, tm1 = -1e30f;
        #pragma unroll
        for (int n8 = 0; n8 < 8; n8++) {
            tm0 = fmaxf(tm0, fmaxf(s[n8][0], s[n8][1]));
            tm1 = fmaxf(tm1, fmaxf(s[n8][2], s[n8][3]));
        }
        tm0 = fmaxf(tm0, __shfl_xor_sync(0xFFFFFFFF, tm0, 1));
        tm0 = fmaxf(tm0, __shfl_xor_sync(0xFFFFFFFF, tm0, 2));
        tm1 = fmaxf(tm1, __shfl_xor_sync(0xFFFFFFFF, tm1, 1));
        tm1 = fmaxf(tm1, __shfl_xor_sync(0xFFFFFFFF, tm1, 2));
        float mn0 = fmaxf(m0, tm0), mn1 = fmaxf(m1, tm1);
        float al0 = __expf(m0 - mn0), al1 = __expf(m1 - mn1);
        m0 = mn0; m1 = mn1;
        float sum0 = 0.f, sum1 = 0.f;
        #pragma unroll
        for (int n8 = 0; n8 < 8; n8++) {
            s[n8][0] = __expf(s[n8][0] - mn0);
            s[n8][1] = __expf(s[n8][1] - mn0);
            s[n8][2] = __expf(s[n8][2] - mn1);
            s[n8][3] = __expf(s[n8][3] - mn1);
            sum0 += s[n8][0] + s[n8][1];
            sum1 += s[n8][2] + s[n8][3];
        }
        sum0 += __shfl_xor_sync(0xFFFFFFFF, sum0, 1);
        sum0 += __shfl_xor_sync(0xFFFFFFFF, sum0, 2);
        sum1 += __shfl_xor_sync(0xFFFFFFFF, sum1, 1);
        sum1 += __shfl_xor_sync(0xFFFFFFFF, sum1, 2);
        l0 = l0 * al0 + sum0;
        l1 = l1 * al1 + sum1;
        #pragma unroll
        for (int n8 = 0; n8 < 8; n8++) {
            acc_o[n8][0] *= al0; acc_o[n8][1] *= al0;
            acc_o[n8][2] *= al1; acc_o[n8][3] *= al1;
        }

        uint32_t pah[4][4], pal[4][4];
        #pragma unroll
        for (int j = 0; j < 4; j++) {
            int e = 2 * j, o = 2 * j + 1;
            split2(s[e][0], s[e][1], pah[j][0], pal[j][0]);
            split2(s[e][2], s[e][3], pah[j][1], pal[j][1]);
            split2(s[o][0], s[o][1], pah[j][2], pal[j][2]);
            split2(s[o][2], s[o][3], pah[j][3], pal[j][3]);
        }

        #pragma unroll
        for (int ks = 0; ks < 4; ks++) {
            #pragma unroll
            for (int nt = 0; nt < 4; nt++) {
                uint32_t vfh[4], vfl[4];
                uint32_t veo = (uint32_t)((ks * 16 + (lane & 15)) * ATSTR
                                          + (nt * 16 + fr_col8) * 2);
                ldsm4t(vfh, sb + AT_VH + buf * AT_TILE + veo);
                ldsm4t(vfl, sb + AT_VL + buf * AT_TILE + veo);
                mma2(acc_o[nt * 2],     pah[ks], vfh[0], vfh[1]);
                mma2(acc_o[nt * 2],     pah[ks], vfl[0], vfl[1]);
                mma2(acc_o[nt * 2],     pal[ks], vfh[0], vfh[1]);
                mma2(acc_o[nt * 2 + 1], pah[ks], vfh[2], vfh[3]);
                mma2(acc_o[nt * 2 + 1], pah[ks], vfl[2], vfl[3]);
                mma2(acc_o[nt * 2 + 1], pal[ks], vfh[2], vfh[3]);
            }
        }
        __syncthreads();
    }

    float il0 = 1.f / l0, il1 = 1.f / l1;
    size_t o0 = (rowbase + (size_t)r0g) * DDIM + hcol;
    size_t o1 = (rowbase + (size_t)r1g) * DDIM + hcol;
    #pragma unroll
    for (int nt = 0; nt < 8; nt++) {
        int c = nt * 8 + (lane & 3) * 2;
        uint32_t h0, lo0, h1, lo1;
        split2(acc_o[nt][0] * il0, acc_o[nt][1] * il0, h0, lo0);
        split2(acc_o[nt][2] * il1, acc_o[nt][3] * il1, h1, lo1);
        *(uint32_t*)(oh + o0 + c) = h0;
        *(uint32_t*)(ol + o0 + c) = lo0;
        *(uint32_t*)(oh + o1 + c) = h1;
        *(uint32_t*)(ol + o1 + c) = lo1;
    }
#undef LOADT
}

// ---------------- host orchestration ----------------------------------------
extern "C" void kernel_launch(void* const* d_in, const int* in_sizes, int n_in,
                              void* d_out, int out_size)
{
    const int*   ids   = (const int*)  d_in[0];
    const float* tok   = (const float*)d_in[1];
    const float* pos   = (const float*)d_in[2];
    const float* Wq    = (const float*)d_in[3];
    const float* bq    = (const float*)d_in[4];
    const float* Wk    = (const float*)d_in[5];
    const float* bk    = (const float*)d_in[6];
    const float* Wv    = (const float*)d_in[7];
    const float* bv    = (const float*)d_in[8];
    const float* Wo    = (const float*)d_in[9];
    const float* bo    = (const float*)d_in[10];
    const float* W1    = (const float*)d_in[11];
    const float* b1    = (const float*)d_in[12];
    const float* W2    = (const float*)d_in[13];
    const float* b2    = (const float*)d_in[14];
    const float* ln1g  = (const float*)d_in[15];
    const float* ln1b  = (const float*)d_in[16];
    const float* ln2g  = (const float*)d_in[17];
    const float* ln2b  = (const float*)d_in[18];
    const float* lnfg  = (const float*)d_in[19];
    const float* lnfb  = (const float*)d_in[20];
    const float* Wout  = (const float*)d_in[21];
    const float* bout  = (const float*)d_in[22];
    float* out = (float*)d_out;

    float *x;
    __nv_bfloat16 *hh, *hl, *qkvh, *qkvl, *atth, *attl, *midh, *midl;
    __nv_bfloat16 *wqkvh, *wqkvl, *woh, *wol;
    __nv_bfloat16 *w1h, *w1l, *w2h, *w2l, *wouth, *woutl;
    cudaGetSymbolAddress((void**)&x, g_x);
    cudaGetSymbolAddress((void**)&hh, g_hh);
    cudaGetSymbolAddress((void**)&hl, g_hl);
    cudaGetSymbolAddress((void**)&qkvh, g_qkvh);
    cudaGetSymbolAddress((void**)&qkvl, g_qkvl);
    cudaGetSymbolAddress((void**)&atth, g_atth);
    cudaGetSymbolAddress((void**)&attl, g_attl);
    cudaGetSymbolAddress((void**)&midh, g_midh);
    cudaGetSymbolAddress((void**)&midl, g_midl);
    cudaGetSymbolAddress((void**)&wqkvh, g_wqkvh);
    cudaGetSymbolAddress((void**)&wqkvl, g_wqkvl);
    cudaGetSymbolAddress((void**)&woh, g_woh);
    cudaGetSymbolAddress((void**)&wol, g_wol);
    cudaGetSymbolAddress((void**)&w1h, g_w1h);
    cudaGetSymbolAddress((void**)&w1l, g_w1l);
    cudaGetSymbolAddress((void**)&w2h, g_w2h);
    cudaGetSymbolAddress((void**)&w2l, g_w2l);
    cudaGetSymbolAddress((void**)&wouth, g_wouth);
    cudaGetSymbolAddress((void**)&woutl, g_woutl);

    const size_t WZ = (size_t)LNUM * DDIM * DDIM;
    const size_t CZ = (size_t)MROWS * DDIM;
    __nv_bfloat16* qh = qkvh;            __nv_bfloat16* ql_ = qkvl;
    __nv_bfloat16* kh = qkvh + CZ;       __nv_bfloat16* kl = qkvl + CZ;
    __nv_bfloat16* vh = qkvh + 2 * CZ;   __nv_bfloat16* vl = qkvl + 2 * CZ;

    cudaFuncSetAttribute(attn_mma, cudaFuncAttributeMaxDynamicSharedMemorySize, AT_SMEM);
    cudaFuncSetAttribute(gemm_as<false, false, false>, cudaFuncAttributeMaxDynamicSharedMemorySize, SMEM_MM);
    cudaFuncSetAttribute(gemm_as<false, true,  false>, cudaFuncAttributeMaxDynamicSharedMemorySize, SMEM_MM);
    cudaFuncSetAttribute(gemm_as<true,  false, true >, cudaFuncAttributeMaxDynamicSharedMemorySize, SMEM_MM);
    cudaFuncSetAttribute(gemm_as<false, false, true >, cudaFuncAttributeMaxDynamicSharedMemorySize, SMEM_MM);

    // one-shot weight conversion: single fused launch
    const int nDD4 = LNUM * DDIM * DDIM / 4;
    const int nDF4 = LNUM * DDIM * FDIM / 4;
    const int nV4  = DDIM * VDIM / 4;
    {
        dim3 gs(2048, 7);
        split_all_kernel<<<gs, 256>>>(
            (const float4*)Wq, (uint2*)wqkvh, (uint2*)wqkvl, nDD4,
            (const float4*)Wk, (uint2*)(wqkvh + WZ), (uint2*)(wqkvl + WZ), nDD4,
            (const float4*)Wv, (uint2*)(wqkvh + 2 * WZ), (uint2*)(wqkvl + 2 * WZ), nDD4,
            (const float4*)Wo, (uint2*)woh, (uint2*)wol, nDD4,
            (const float4*)W1, (uint2*)w1h, (uint2*)w1l, nDF4,
            (const float4*)W2, (uint2*)w2h, (uint2*)w2l, nDF4,
            (const float4*)Wout, (uint2*)wouth, (uint2*)woutl, nV4);
    }

    embed_kernel<<<MROWS, 256>>>(ids, tok, pos, x);

    dim3 gQKV(DDIM / BN, MROWS / BM, 3);
    dim3 gD (DDIM / BN, MROWS / BM);
    dim3 gF (FDIM / BN, MROWS / BM);
    dim3 gV (VDIM / BN, MROWS / BM);
    dim3 gAtt(SDIM / TQ, HNUM, BNUM);
    const int gLN = MROWS / 8;   // warp per row, 8 rows per block

    for (int l = 0; l < LNUM; l++) {
        size_t oDD = (size_t)l * DDIM * DDIM;
        size_t oDF = (size_t)l * DDIM * FDIM;

        ln_kernel<<<gLN, 256>>>(x, ln1g + l * DDIM, ln1b + l * DDIM, hh, hl);

        gemm_as<false, false, true><<<gQKV, 256, SMEM_MM>>>(
            hh, hl, wqkvh + oDD, wqkvl + oDD, WZ,
            bq + l * DDIM, bk + l * DDIM, bv + l * DDIM,
            nullptr, CZ, qkvh, qkvl, MROWS, DDIM, DDIM);

        attn_mma<<<gAtt, 256, AT_SMEM>>>(qh, ql_, kh, kl, vh, vl, atth, attl);

        gemm_as<false, true, false><<<gD, 256, SMEM_MM>>>(
            atth, attl, woh + oDD, wol + oDD, 0,
            bo + l * DDIM, nullptr, nullptr,
            x, 0, nullptr, nullptr, MROWS, DDIM, DDIM);

        ln_kernel<<<gLN, 256>>>(x, ln2g + l * DDIM, ln2b + l * DDIM, hh, hl);

        gemm_as<true, false, true><<<gF, 256, SMEM_MM>>>(
            hh, hl, w1h + oDF, w1l + oDF, 0,
            b1 + l * FDIM, nullptr, nullptr,
            nullptr, 0, midh, midl, MROWS, FDIM, DDIM);

        gemm_as<false, true, false><<<gD, 256, SMEM_MM>>>(
            midh, midl, w2h + oDF, w2l + oDF, 0,
            b2 + l * DDIM, nullptr, nullptr,
            x, 0, nullptr, nullptr, MROWS, DDIM, FDIM);
    }

    ln_kernel<<<gLN, 256>>>(x, lnfg, lnfb, hh, hl);
    gemm_as<false, false, false><<<gV, 256, SMEM_MM>>>(
        hh, hl, wouth, woutl, 0,
        bout, nullptr, nullptr,
        out, 0, nullptr, nullptr, MROWS, VDIM, DDIM);
}

// round 16
// speedup vs baseline: 1.3019x; 1.3019x over previous
#include <cuda_runtime.h>
#include <cuda_bf16.h>
#include <math.h>
#include <stdint.h>

// Problem constants
#define LNUM 8
#define DDIM 1024
#define HNUM 16
#define DKDIM 64
#define FDIM 4096
#define VDIM 32000
#define SDIM 1024
#define BNUM 2
#define MROWS (BNUM * SDIM)   // 2048

// ---------------- scratch (device globals; no runtime allocation) ----------
__device__ float g_x[MROWS * DDIM];
__device__ __nv_bfloat16 g_hh  [MROWS * DDIM];
__device__ __nv_bfloat16 g_hl  [MROWS * DDIM];
__device__ __nv_bfloat16 g_qkvh[3 * MROWS * DDIM];
__device__ __nv_bfloat16 g_qkvl[3 * MROWS * DDIM];
__device__ __nv_bfloat16 g_atth[MROWS * DDIM];
__device__ __nv_bfloat16 g_attl[MROWS * DDIM];
__device__ __nv_bfloat16 g_midh[MROWS * FDIM];
__device__ __nv_bfloat16 g_midl[MROWS * FDIM];
__device__ __nv_bfloat16 g_wqkvh[3 * LNUM * DDIM * DDIM];
__device__ __nv_bfloat16 g_wqkvl[3 * LNUM * DDIM * DDIM];
__device__ __nv_bfloat16 g_woh[LNUM * DDIM * DDIM];
__device__ __nv_bfloat16 g_wol[LNUM * DDIM * DDIM];
__device__ __nv_bfloat16 g_w1h[LNUM * DDIM * FDIM];
__device__ __nv_bfloat16 g_w1l[LNUM * DDIM * FDIM];
__device__ __nv_bfloat16 g_w2h[LNUM * DDIM * FDIM];
__device__ __nv_bfloat16 g_w2l[LNUM * DDIM * FDIM];
__device__ __nv_bfloat16 g_wouth[DDIM * VDIM];
__device__ __nv_bfloat16 g_woutl[DDIM * VDIM];

// ======================= PTX helpers (portable, sm_80+) =====================
__device__ __forceinline__ uint32_t smem_u32(const void* p) {
    uint32_t a;
    asm("{ .reg .u64 t; cvta.to.shared.u64 t, %1; cvt.u32.u64 %0, t; }"
        : "=r"(a) : "l"(p));
    return a;
}
__device__ __forceinline__ void ldsm4(uint32_t* r, uint32_t addr) {
    asm volatile("ldmatrix.sync.aligned.m8n8.x4.shared.b16 {%0,%1,%2,%3}, [%4];"
        : "=r"(r[0]), "=r"(r[1]), "=r"(r[2]), "=r"(r[3]) : "r"(addr));
}
__device__ __forceinline__ void ldsm4t(uint32_t* r, uint32_t addr) {
    asm volatile("ldmatrix.sync.aligned.m8n8.x4.trans.shared.b16 {%0,%1,%2,%3}, [%4];"
        : "=r"(r[0]), "=r"(r[1]), "=r"(r[2]), "=r"(r[3]) : "r"(addr));
}
__device__ __forceinline__ void mma16816(float* c, const uint32_t* a,
                                         const uint32_t* b) {
    asm volatile(
        "mma.sync.aligned.m16n8k16.row.col.f32.bf16.bf16.f32 "
        "{%0,%1,%2,%3}, {%4,%5,%6,%7}, {%8,%9}, {%0,%1,%2,%3};"
        : "+f"(c[0]), "+f"(c[1]), "+f"(c[2]), "+f"(c[3])
        : "r"(a[0]), "r"(a[1]), "r"(a[2]), "r"(a[3]), "r"(b[0]), "r"(b[1]));
}
__device__ __forceinline__ void mma2(float* c, const uint32_t* a,
                                     uint32_t b0, uint32_t b1) {
    asm volatile(
        "mma.sync.aligned.m16n8k16.row.col.f32.bf16.bf16.f32 "
        "{%0,%1,%2,%3}, {%4,%5,%6,%7}, {%8,%9}, {%0,%1,%2,%3};"
        : "+f"(c[0]), "+f"(c[1]), "+f"(c[2]), "+f"(c[3])
        : "r"(a[0]), "r"(a[1]), "r"(a[2]), "r"(a[3]), "r"(b0), "r"(b1));
}
__device__ __forceinline__ void cpa16(uint32_t d, const void* s) {
    asm volatile("cp.async.cg.shared.global [%0], [%1], 16;" :: "r"(d), "l"(s));
}
#define CP_COMMIT() asm volatile("cp.async.commit_group;" ::: "memory")
#define CP_WAIT2()  asm volatile("cp.async.wait_group 2;" ::: "memory")
#define CP_WAIT1()  asm volatile("cp.async.wait_group 1;" ::: "memory")

__device__ __forceinline__ uint32_t packbf2(__nv_bfloat16 a, __nv_bfloat16 b) {
    __nv_bfloat162 t;
    t.x = a; t.y = b;
    return *reinterpret_cast<uint32_t*>(&t);
}
// pack 2 fp32 into bf16x2 hi word + lo (residual) word
__device__ __forceinline__ void split2(float x, float y, uint32_t& h, uint32_t& l) {
    __nv_bfloat16 hx = __float2bfloat16(x);
    __nv_bfloat16 hy = __float2bfloat16(y);
    h = packbf2(hx, hy);
    l = packbf2(__float2bfloat16(x - __bfloat162float(hx)),
                __float2bfloat16(y - __bfloat162float(hy)));
}
__device__ __forceinline__ void cvt_split4(float4 v, uint32_t& h01, uint32_t& h23,
                                           uint32_t& l01, uint32_t& l23) {
    split2(v.x, v.y, h01, l01);
    split2(v.z, v.w, h23, l23);
}

// ---------------- fused split kernel: all 7 weight tensors in one launch ----
__global__ void split_all_kernel(
    const float4* s0, uint2* h0, uint2* l0, int n0,
    const float4* s1, uint2* h1, uint2* l1, int n1,
    const float4* s2, uint2* h2, uint2* l2, int n2,
    const float4* s3, uint2* h3, uint2* l3, int n3,
    const float4* s4, uint2* h4, uint2* l4, int n4,
    const float4* s5, uint2* h5, uint2* l5, int n5,
    const float4* s6, uint2* h6, uint2* l6, int n6)
{
    const float4* src; uint2* hi; uint2* lo; int n;
    switch (blockIdx.y) {
        case 0: src = s0; hi = h0; lo = l0; n = n0; break;
        case 1: src = s1; hi = h1; lo = l1; n = n1; break;
        case 2: src = s2; hi = h2; lo = l2; n = n2; break;
        case 3: src = s3; hi = h3; lo = l3; n = n3; break;
        case 4: src = s4; hi = h4; lo = l4; n = n4; break;
        case 5: src = s5; hi = h5; lo = l5; n = n5; break;
        default: src = s6; hi = h6; lo = l6; n = n6; break;
    }
    int i = blockIdx.x * blockDim.x + threadIdx.x;
    int stride = gridDim.x * blockDim.x;
    for (; i < n; i += stride) {
        float4 v = src[i];
        uint32_t a01, a23, b01, b23;
        cvt_split4(v, a01, a23, b01, b23);
        hi[i] = make_uint2(a01, a23);
        lo[i] = make_uint2(b01, b23);
    }
}

// ---------------- async-pipelined tensor-core GEMM --------------------------
#define BM 128
#define BN 128
#define BK 32
#define A_STG 10240
#define B_STG 8704
#define ALO_OFF (4 * A_STG)
#define BHI_OFF (2 * ALO_OFF)
#define BLO_OFF (BHI_OFF + 4 * B_STG)
#define SMEM_MM (BLO_OFF + 4 * B_STG)   // 151552 bytes

struct Frag {
    uint32_t ah[4][4];
    uint32_t al[4][4];
    uint32_t bh[2][4];
    uint32_t bl[2][4];
};

template<bool RELU, bool RES, bool OBF>
__global__ void __launch_bounds__(256, 1)
gemm_as(const __nv_bfloat16* __restrict__ Ah, const __nv_bfloat16* __restrict__ Al,
        const __nv_bfloat16* __restrict__ Bh0, const __nv_bfloat16* __restrict__ Bl0,
        size_t wz,
        const float* __restrict__ bias0, const float* __restrict__ bias1,
        const float* __restrict__ bias2,
        float* __restrict__ C0, size_t cz,
        __nv_bfloat16* __restrict__ Ch0, __nv_bfloat16* __restrict__ Cl0,
        int M, int N, int K)
{
    extern __shared__ char smem[];
    uint32_t sb = smem_u32(smem);

    int tid  = threadIdx.x;
    int wid  = tid >> 5;
    int lane = tid & 31;
    int z    = blockIdx.z;
    int bn = blockIdx.x * BN;
    int bm = blockIdx.y * BM;
    int wm = (wid >> 2) * 64;
    int wn = (wid & 3) * 32;

    const __nv_bfloat16* Bh = Bh0 + (size_t)z * wz;
    const __nv_bfloat16* Bl = Bl0 + (size_t)z * wz;
    const float* bias = (z == 0) ? bias0 : (z == 1) ? bias1 : bias2;

    const __nv_bfloat16* aH = Ah + (size_t)(bm + (tid >> 1)) * K + (tid & 1) * 16;
    const __nv_bfloat16* aL = Al + (size_t)(bm + (tid >> 1)) * K + (tid & 1) * 16;
    const __nv_bfloat16* bH = Bh + (size_t)(tid >> 3) * N + bn + (tid & 7) * 16;
    const __nv_bfloat16* bL = Bl + (size_t)(tid >> 3) * N + bn + (tid & 7) * 16;
    uint32_t adst = sb + (uint32_t)((tid >> 1) * 80 + (tid & 1) * 32);
    uint32_t bdst = sb + BHI_OFF + (uint32_t)((tid >> 3) * 272 + (tid & 7) * 32);

    const int nst = K / BK;

#define LOADS(s)                                                              \
    {                                                                         \
        if ((s) < nst) {                                                      \
            int buf_ = (s) & 3;                                               \
            uint32_t ad = adst + buf_ * A_STG;                                \
            const __nv_bfloat16* a1 = aH + (s) * BK;                          \
            const __nv_bfloat16* a2 = aL + (s) * BK;                          \
            cpa16(ad, a1); cpa16(ad + 16, a1 + 8);                            \
            cpa16(ad + ALO_OFF, a2); cpa16(ad + ALO_OFF + 16, a2 + 8);        \
            uint32_t bd = bdst + buf_ * B_STG;                                \
            const __nv_bfloat16* b1 = bH + (size_t)(s) * BK * N;              \
            const __nv_bfloat16* b2 = bL + (size_t)(s) * BK * N;              \
            cpa16(bd, b1); cpa16(bd + 16, b1 + 8);                            \
            cpa16(bd + (BLO_OFF - BHI_OFF), b2);                              \
            cpa16(bd + (BLO_OFF - BHI_OFF) + 16, b2 + 8);                     \
        }                                                                     \
        CP_COMMIT();                                                          \
    }

    int fr_arow = wm + (lane & 15);
    int fr_acol = (lane >> 4) * 8;
    int fr_krow = (lane & 15);
    int fr_ncol = wn + (lane >> 4) * 8;

#define LDFRAG(f, buf, kk)                                                    \
    {                                                                         \
        uint32_t ab_ = sb + (buf) * A_STG;                                    \
        int kc_ = (kk) * 16 + fr_acol;                                        \
        _Pragma("unroll")                                                     \
        for (int mt = 0; mt < 4; mt++) {                                      \
            uint32_t eo = (uint32_t)((fr_arow + mt * 16) * 40 + kc_) * 2;     \
            ldsm4((f).ah[mt], ab_ + eo);                                      \
            ldsm4((f).al[mt], ab_ + ALO_OFF + eo);                            \
        }                                                                     \
        uint32_t bb_ = sb + BHI_OFF + (buf) * B_STG;                          \
        int kr_ = (kk) * 16 + fr_krow;                                        \
        _Pragma("unroll")                                                     \
        for (int nt2 = 0; nt2 < 2; nt2++) {                                   \
            uint32_t eo = (uint32_t)(kr_ * 136 + fr_ncol + nt2 * 16) * 2;     \
            ldsm4t((f).bh[nt2], bb_ + eo);                                    \
            ldsm4t((f).bl[nt2], bb_ + (BLO_OFF - BHI_OFF) + eo);              \
        }                                                                     \
    }

#define DOMMA(f)                                                              \
    {                                                                         \
        _Pragma("unroll")                                                     \
        for (int mt = 0; mt < 4; mt++)                                        \
            _Pragma("unroll")                                                 \
            for (int nt = 0; nt < 4; nt++) {                                  \
                const uint32_t* bhp = &(f).bh[nt >> 1][(nt & 1) * 2];         \
                const uint32_t* blp = &(f).bl[nt >> 1][(nt & 1) * 2];         \
                mma16816(acc[mt][nt], (f).ah[mt], bhp);                       \
                mma16816(acc[mt][nt], (f).ah[mt], blp);                       \
                mma16816(acc[mt][nt], (f).al[mt], bhp);                       \
            }                                                                 \
    }

    float acc[4][4][4];
    #pragma unroll
    for (int i = 0; i < 4; i++)
        #pragma unroll
        for (int j = 0; j < 4; j++)
            #pragma unroll
            for (int r = 0; r < 4; r++) acc[i][j][r] = 0.f;

    Frag fr0, fr1;

    LOADS(0); LOADS(1); LOADS(2);
    CP_WAIT2();
    __syncthreads();
    LDFRAG(fr0, 0, 0);

    for (int s = 0; s < nst; s++) {
        int buf = s & 3;
        LDFRAG(fr1, buf, 1);
        DOMMA(fr0);
        LOADS(s + 3);
        CP_WAIT2();
        __syncthreads();
        if (s + 1 < nst) LDFRAG(fr0, (s + 1) & 3, 0);
        DOMMA(fr1);
    }

    // ---- epilogue ----
    #pragma unroll
    for (int mt = 0; mt < 4; mt++) {
        int grow = bm + wm + mt * 16 + (lane >> 2);
        #pragma unroll
        for (int nt = 0; nt < 4; nt++) {
            int gcol = bn + wn + nt * 8 + (lane & 3) * 2;
            float2 bb = *(const float2*)(bias + gcol);
            float v0 = acc[mt][nt][0] + bb.x;
            float v1 = acc[mt][nt][1] + bb.y;
            float v2 = acc[mt][nt][2] + bb.x;
            float v3 = acc[mt][nt][3] + bb.y;
            if (RELU) {
                v0 = fmaxf(v0, 0.f); v1 = fmaxf(v1, 0.f);
                v2 = fmaxf(v2, 0.f); v3 = fmaxf(v3, 0.f);
            }
            if (OBF) {
                __nv_bfloat16* Ch = Ch0 + (size_t)z * cz;
                __nv_bfloat16* Cl = Cl0 + (size_t)z * cz;
                size_t o0 = (size_t)grow * N + gcol;
                size_t o1 = (size_t)(grow + 8) * N + gcol;
                uint32_t h0, l0, h1, l1;
                split2(v0, v1, h0, l0);
                split2(v2, v3, h1, l1);
                *(uint32_t*)(Ch + o0) = h0;
                *(uint32_t*)(Cl + o0) = l0;
                *(uint32_t*)(Ch + o1) = h1;
                *(uint32_t*)(Cl + o1) = l1;
            } else {
                float* C = C0 + (size_t)z * cz;
                float* c0 = C + (size_t)grow * N;
                float* c1 = C + (size_t)(grow + 8) * N;
                if (RES) {
                    float2 o0 = *(const float2*)(c0 + gcol);
                    float2 o1 = *(const float2*)(c1 + gcol);
                    v0 += o0.x; v1 += o0.y; v2 += o1.x; v3 += o1.y;
                }
                *(float2*)(c0 + gcol) = make_float2(v0, v1);
                *(float2*)(c1 + gcol) = make_float2(v2, v3);
            }
        }
    }
#undef LOADS
#undef LDFRAG
#undef DOMMA
}

// ---------------- embedding -------------------------------------------------
__global__ void embed_kernel(const int* __restrict__ ids,
                             const float* __restrict__ tok,
                             const float* __restrict__ pos,
                             float* __restrict__ x)
{
    int row = blockIdx.x;
    int s   = row % SDIM;
    int id  = ids[row];
    int tid = threadIdx.x;
    const float* tr = tok + (size_t)id * DDIM;
    const float* pr = pos + (size_t)s  * DDIM;
    float* xr = x + (size_t)row * DDIM;
    #pragma unroll
    for (int i = 0; i < 4; i++) {
        int c = tid + i * 256;
        xr[c] = tr[c] + pr[c];
    }
}

// ---------------- layernorm: warp per row, shfl reductions ------------------
__global__ void ln_kernel(const float* __restrict__ x,
                          const float* __restrict__ g,
                          const float* __restrict__ b,
                          __nv_bfloat16* __restrict__ oh,
                          __nv_bfloat16* __restrict__ ol)
{
    int wid  = threadIdx.x >> 5;
    int lane = threadIdx.x & 31;
    int row  = blockIdx.x * 8 + wid;

    const float4* xr = (const float4*)(x + (size_t)row * DDIM);
    float4 v[8];
    float s = 0.f;
    #pragma unroll
    for (int i = 0; i < 8; i++) {
        v[i] = xr[lane + 32 * i];
        s += v[i].x + v[i].y + v[i].z + v[i].w;
    }
    #pragma unroll
    for (int o = 16; o > 0; o >>= 1) s += __shfl_xor_sync(0xFFFFFFFF, s, o);
    float mean = s * (1.0f / DDIM);

    float vs = 0.f;
    #pragma unroll
    for (int i = 0; i < 8; i++) {
        float dx = v[i].x - mean, dy = v[i].y - mean;
        float dz = v[i].z - mean, dw = v[i].w - mean;
        vs += dx * dx + dy * dy + dz * dz + dw * dw;
    }
    #pragma unroll
    for (int o = 16; o > 0; o >>= 1) vs += __shfl_xor_sync(0xFFFFFFFF, vs, o);
    float inv = rsqrtf(vs * (1.0f / DDIM) + 1e-5f);

    uint2* ohp = (uint2*)(oh + (size_t)row * DDIM);
    uint2* olp = (uint2*)(ol + (size_t)row * DDIM);
    const float4* gp = (const float4*)g;
    const float4* bp = (const float4*)b;
    #pragma unroll
    for (int i = 0; i < 8; i++) {
        int c4 = lane + 32 * i;
        float4 gg = gp[c4];
        float4 bb = bp[c4];
        float4 o4;
        o4.x = (v[i].x - mean) * inv * gg.x + bb.x;
        o4.y = (v[i].y - mean) * inv * gg.y + bb.y;
        o4.z = (v[i].z - mean) * inv * gg.z + bb.z;
        o4.w = (v[i].w - mean) * inv * gg.w + bb.w;
        uint32_t h01, h23, l01, l23;
        cvt_split4(o4, h01, h23, l01, l23);
        ohp[c4] = make_uint2(h01, h23);
        olp[c4] = make_uint2(l01, l23);
    }
}

// ---------------- tensor-core flash attention --------------------------------
#define TQ 128
#define TKT 64
#define ATSTR 144
#define AT_QH 0u
#define AT_QL (TQ * ATSTR)
#define AT_KH (2u * TQ * ATSTR)
#define AT_TILE (TKT * ATSTR)
#define AT_KL (AT_KH + 2 * AT_TILE)
#define AT_VH (AT_KL + 2 * AT_TILE)
#define AT_VL (AT_VH + 2 * AT_TILE)
#define AT_SMEM (AT_VL + 2 * AT_TILE)  // 110592 bytes

__global__ void __launch_bounds__(256, 1)
attn_mma(const __nv_bfloat16* __restrict__ qh, const __nv_bfloat16* __restrict__ ql,
         const __nv_bfloat16* __restrict__ kh, const __nv_bfloat16* __restrict__ kl,
         const __nv_bfloat16* __restrict__ vh, const __nv_bfloat16* __restrict__ vl,
         __nv_bfloat16* __restrict__ oh, __nv_bfloat16* __restrict__ ol)
{
    extern __shared__ char smem[];
    uint32_t sb = smem_u32(smem);
    int tid = threadIdx.x, wid = tid >> 5, lane = tid & 31;
    int qt = gridDim.x - 1 - blockIdx.x;
    int hhd = blockIdx.y, bb = blockIdx.z;
    int hcol = hhd * DKDIM;
    size_t rowbase = (size_t)bb * SDIM;
    int q0 = qt * TQ;

    {
        int r = tid >> 1, hf = (tid & 1) * 32;
        const __nv_bfloat16* s1 = qh + (rowbase + q0 + r) * DDIM + hcol + hf;
        const __nv_bfloat16* s2 = ql + (rowbase + q0 + r) * DDIM + hcol + hf;
        uint32_t d = sb + AT_QH + (uint32_t)(r * ATSTR + hf * 2);
        cpa16(d, s1); cpa16(d + 16, s1 + 8);
        cpa16(d + 32, s1 + 16); cpa16(d + 48, s1 + 24);
        d += AT_QL;
        cpa16(d, s2); cpa16(d + 16, s2 + 8);
        cpa16(d + 32, s2 + 16); cpa16(d + 48, s2 + 24);
    }
    int lr = tid >> 2;
    int lq = (tid & 3) * 16;
#define LOADT(kt_, buf_)                                                      \
    {                                                                         \
        size_t so = (rowbase + (kt_) * TKT + lr) * DDIM + hcol + lq;          \
        uint32_t dd = (uint32_t)(lr * ATSTR + lq * 2);                        \
        uint32_t db = sb + (buf_) * AT_TILE + dd;                             \
        cpa16(db + AT_KH, kh + so); cpa16(db + AT_KH + 16, kh + so + 8);      \
        cpa16(db + AT_KL, kl + so); cpa16(db + AT_KL + 16, kl + so + 8);      \
        cpa16(db + AT_VH, vh + so); cpa16(db + AT_VH + 16, vh + so + 8);      \
        cpa16(db + AT_VL, vl + so); cpa16(db + AT_VL + 16, vl + so + 8);      \
    }
    LOADT(0, 0);
    CP_COMMIT();

    const int ktmax = 2 * qt + 1;
    float m0 = -1e30f, m1 = -1e30f, l0 = 0.f, l1 = 0.f;
    float acc_o[8][4];
    #pragma unroll
    for (int i = 0; i < 8; i++)
        #pragma unroll
        for (int j = 0; j < 4; j++) acc_o[i][j] = 0.f;

    int fr_row = wid * 16 + (lane & 15);
    int fr_col8 = (lane >> 4) * 8;
    int r0g = q0 + wid * 16 + (lane >> 2);
    int r1g = r0g + 8;

    for (int kt = 0; kt <= ktmax; kt++) {
        int buf = kt & 1;
        if (kt < ktmax) LOADT(kt + 1, buf ^ 1);
        CP_COMMIT();
        CP_WAIT1();
        __syncthreads();

        float s[8][4];
        #pragma unroll
        for (int i = 0; i < 8; i++)
            #pragma unroll
            for (int j = 0; j < 4; j++) s[i][j] = 0.f;

        #pragma unroll
        for (int ks = 0; ks < 4; ks++) {
            uint32_t qfh[4], qfl[4];
            uint32_t qeo = (uint32_t)(fr_row * ATSTR + (ks * 16 + fr_col8) * 2);
            ldsm4(qfh, sb + AT_QH + qeo);
            ldsm4(qfl, sb + AT_QL + qeo);
            #pragma unroll
            for (int nt = 0; nt < 4; nt++) {
                uint32_t kfh[4], kfl[4];
                uint32_t keo = (uint32_t)((nt * 16 + (lane & 15)) * ATSTR
                                          + (ks * 16 + fr_col8) * 2);
                ldsm4(kfh, sb + AT_KH + buf * AT_TILE + keo);
                ldsm4(kfl, sb + AT_KL + buf * AT_TILE + keo);
                mma2(s[nt * 2],     qfh, kfh[0], kfh[2]);
                mma2(s[nt * 2],     qfh, kfl[0], kfl[2]);
                mma2(s[nt * 2],     qfl, kfh[0], kfh[2]);
                mma2(s[nt * 2 + 1], qfh, kfh[1], kfh[3]);
                mma2(s[nt * 2 + 1], qfh, kfl[1], kfl[3]);
                mma2(s[nt * 2 + 1], qfl, kfh[1], kfh[3]);
            }
        }

        const float sc = 0.125f;
        bool msk = (kt >= 2 * qt);
        #pragma unroll
        for (int n8 = 0; n8 < 8; n8++) {
            int kc = kt * TKT + n8 * 8 + (lane & 3) * 2;
            s[n8][0] *= sc; s[n8][1] *= sc; s[n8][2] *= sc; s[n8][3] *= sc;
            if (msk) {
                if (kc     > r0g) s[n8][0] = -1e30f;
                if (kc + 1 > r0g) s[n8][1] = -1e30f;
                if (kc     > r1g) s[n8][2] = -1e30f;
                if (kc + 1 > r1g) s[n8][3] = -1e30f;
            }
        }

        float tm0 = -1e30f, tm1 = -1e30f;
        #pragma unroll
        for (int n8 = 0; n8 < 8; n8++) {
            tm0 = fmaxf(tm0, fmaxf(s[n8][0], s[n8][1]));
            tm1 = fmaxf(tm1, fmaxf(s[n8][2], s[n8][3]));
        }
        tm0 = fmaxf(tm0, __shfl_xor_sync(0xFFFFFFFF, tm0, 1));
        tm0 = fmaxf(tm0, __shfl_xor_sync(0xFFFFFFFF, tm0, 2));
        tm1 = fmaxf(tm1, __shfl_xor_sync(0xFFFFFFFF, tm1, 1));
        tm1 = fmaxf(tm1, __shfl_xor_sync(0xFFFFFFFF, tm1, 2));
        float mn0 = fmaxf(m0, tm0), mn1 = fmaxf(m1, tm1);
        float al0 = __expf(m0 - mn0), al1 = __expf(m1 - mn1);
        m0 = mn0; m1 = mn1;
        float sum0 = 0.f, sum1 = 0.f;
        #pragma unroll
        for (int n8 = 0; n8 < 8; n8++) {
            s[n8][0] = __expf(s[n8][0] - mn0);
            s[n8][1] = __expf(s[n8][1] - mn0);
            s[n8][2] = __expf(s[n8][2] - mn1);
            s[n8][3] = __expf(s[n8][3] - mn1);
            sum0 += s[n8][0] + s[n8][1];
            sum1 += s[n8][2] + s[n8][3];
        }
        sum0 += __shfl_xor_sync(0xFFFFFFFF, sum0, 1);
        sum0 += __shfl_xor_sync(0xFFFFFFFF, sum0, 2);
        sum1 += __shfl_xor_sync(0xFFFFFFFF, sum1, 1);
        sum1 += __shfl_xor_sync(0xFFFFFFFF, sum1, 2);
        l0 = l0 * al0 + sum0;
        l1 = l1 * al1 + sum1;
        #pragma unroll
        for (int n8 = 0; n8 < 8; n8++) {
            acc_o[n8][0] *= al0; acc_o[n8][1] *= al0;
            acc_o[n8][2] *= al1; acc_o[n8][3] *= al1;
        }

        uint32_t pah[4][4], pal[4][4];
        #pragma unroll
        for (int j = 0; j < 4; j++) {
            int e = 2 * j, o = 2 * j + 1;
            split2(s[e][0], s[e][1], pah[j][0], pal[j][0]);
            split2(s[e][2], s[e][3], pah[j][1], pal[j][1]);
            split2(s[o][0], s[o][1], pah[j][2], pal[j][2]);
            split2(s[o][2], s[o][3], pah[j][3], pal[j][3]);
        }

        #pragma unroll
        for (int ks = 0; ks < 4; ks++) {
            #pragma unroll
            for (int nt = 0; nt < 4; nt++) {
                uint32_t vfh[4], vfl[4];
                uint32_t veo = (uint32_t)((ks * 16 + (lane & 15)) * ATSTR
                                          + (nt * 16 + fr_col8) * 2);
                ldsm4t(vfh, sb + AT_VH + buf * AT_TILE + veo);
                ldsm4t(vfl, sb + AT_VL + buf * AT_TILE + veo);
                mma2(acc_o[nt * 2],     pah[ks], vfh[0], vfh[1]);
                mma2(acc_o[nt * 2],     pah[ks], vfl[0], vfl[1]);
                mma2(acc_o[nt * 2],     pal[ks], vfh[0], vfh[1]);
                mma2(acc_o[nt * 2 + 1], pah[ks], vfh[2], vfh[3]);
                mma2(acc_o[nt * 2 + 1], pah[ks], vfl[2], vfl[3]);
                mma2(acc_o[nt * 2 + 1], pal[ks], vfh[2], vfh[3]);
            }
        }
        __syncthreads();
    }

    float il0 = 1.f / l0, il1 = 1.f / l1;
    size_t o0 = (rowbase + (size_t)r0g) * DDIM + hcol;
    size_t o1 = (rowbase + (size_t)r1g) * DDIM + hcol;
    #pragma unroll
    for (int nt = 0; nt < 8; nt++) {
        int c = nt * 8 + (lane & 3) * 2;
        uint32_t h0, lo0, h1, lo1;
        split2(acc_o[nt][0] * il0, acc_o[nt][1] * il0, h0, lo0);
        split2(acc_o[nt][2] * il1, acc_o[nt][3] * il1, h1, lo1);
        *(uint32_t*)(oh + o0 + c) = h0;
        *(uint32_t*)(ol + o0 + c) = lo0;
        *(uint32_t*)(oh + o1 + c) = h1;
        *(uint32_t*)(ol + o1 + c) = lo1;
    }
#undef LOADT
}

// ---------------- host orchestration ----------------------------------------
extern "C" void kernel_launch(void* const* d_in, const int* in_sizes, int n_in,
                              void* d_out, int out_size)
{
    const int*   ids   = (const int*)  d_in[0];
    const float* tok   = (const float*)d_in[1];
    const float* pos   = (const float*)d_in[2];
    const float* Wq    = (const float*)d_in[3];
    const float* bq    = (const float*)d_in[4];
    const float* Wk    = (const float*)d_in[5];
    const float* bk    = (const float*)d_in[6];
    const float* Wv    = (const float*)d_in[7];
    const float* bv    = (const float*)d_in[8];
    const float* Wo    = (const float*)d_in[9];
    const float* bo    = (const float*)d_in[10];
    const float* W1    = (const float*)d_in[11];
    const float* b1    = (const float*)d_in[12];
    const float* W2    = (const float*)d_in[13];
    const float* b2    = (const float*)d_in[14];
    const float* ln1g  = (const float*)d_in[15];
    const float* ln1b  = (const float*)d_in[16];
    const float* ln2g  = (const float*)d_in[17];
    const float* ln2b  = (const float*)d_in[18];
    const float* lnfg  = (const float*)d_in[19];
    const float* lnfb  = (const float*)d_in[20];
    const float* Wout  = (const float*)d_in[21];
    const float* bout  = (const float*)d_in[22];
    float* out = (float*)d_out;

    float *x;
    __nv_bfloat16 *hh, *hl, *qkvh, *qkvl, *atth, *attl, *midh, *midl;
    __nv_bfloat16 *wqkvh, *wqkvl, *woh, *wol;
    __nv_bfloat16 *w1h, *w1l, *w2h, *w2l, *wouth, *woutl;
    cudaGetSymbolAddress((void**)&x, g_x);
    cudaGetSymbolAddress((void**)&hh, g_hh);
    cudaGetSymbolAddress((void**)&hl, g_hl);
    cudaGetSymbolAddress((void**)&qkvh, g_qkvh);
    cudaGetSymbolAddress((void**)&qkvl, g_qkvl);
    cudaGetSymbolAddress((void**)&atth, g_atth);
    cudaGetSymbolAddress((void**)&attl, g_attl);
    cudaGetSymbolAddress((void**)&midh, g_midh);
    cudaGetSymbolAddress((void**)&midl, g_midl);
    cudaGetSymbolAddress((void**)&wqkvh, g_wqkvh);
    cudaGetSymbolAddress((void**)&wqkvl, g_wqkvl);
    cudaGetSymbolAddress((void**)&woh, g_woh);
    cudaGetSymbolAddress((void**)&wol, g_wol);
    cudaGetSymbolAddress((void**)&w1h, g_w1h);
    cudaGetSymbolAddress((void**)&w1l, g_w1l);
    cudaGetSymbolAddress((void**)&w2h, g_w2h);
    cudaGetSymbolAddress((void**)&w2l, g_w2l);
    cudaGetSymbolAddress((void**)&wouth, g_wouth);
    cudaGetSymbolAddress((void**)&woutl, g_woutl);

    const size_t WZ = (size_t)LNUM * DDIM * DDIM;
    const size_t CZ = (size_t)MROWS * DDIM;
    __nv_bfloat16* qh = qkvh;            __nv_bfloat16* ql_ = qkvl;
    __nv_bfloat16* kh = qkvh + CZ;       __nv_bfloat16* kl = qkvl + CZ;
    __nv_bfloat16* vh = qkvh + 2 * CZ;   __nv_bfloat16* vl = qkvl + 2 * CZ;

    cudaFuncSetAttribute(attn_mma, cudaFuncAttributeMaxDynamicSharedMemorySize, AT_SMEM);
    cudaFuncSetAttribute(gemm_as<false, false, false>, cudaFuncAttributeMaxDynamicSharedMemorySize, SMEM_MM);
    cudaFuncSetAttribute(gemm_as<false, true,  false>, cudaFuncAttributeMaxDynamicSharedMemorySize, SMEM_MM);
    cudaFuncSetAttribute(gemm_as<true,  false, true >, cudaFuncAttributeMaxDynamicSharedMemorySize, SMEM_MM);
    cudaFuncSetAttribute(gemm_as<false, false, true >, cudaFuncAttributeMaxDynamicSharedMemorySize, SMEM_MM);

    // one-shot weight conversion: single fused launch
    const int nDD4 = LNUM * DDIM * DDIM / 4;
    const int nDF4 = LNUM * DDIM * FDIM / 4;
    const int nV4  = DDIM * VDIM / 4;
    {
        dim3 gs(2048, 7);
        split_all_kernel<<<gs, 256>>>(
            (const float4*)Wq, (uint2*)wqkvh, (uint2*)wqkvl, nDD4,
            (const float4*)Wk, (uint2*)(wqkvh + WZ), (uint2*)(wqkvl + WZ), nDD4,
            (const float4*)Wv, (uint2*)(wqkvh + 2 * WZ), (uint2*)(wqkvl + 2 * WZ), nDD4,
            (const float4*)Wo, (uint2*)woh, (uint2*)wol, nDD4,
            (const float4*)W1, (uint2*)w1h, (uint2*)w1l, nDF4,
            (const float4*)W2, (uint2*)w2h, (uint2*)w2l, nDF4,
            (const float4*)Wout, (uint2*)wouth, (uint2*)woutl, nV4);
    }

    embed_kernel<<<MROWS, 256>>>(ids, tok, pos, x);

    dim3 gQKV(DDIM / BN, MROWS / BM, 3);
    dim3 gD (DDIM / BN, MROWS / BM);
    dim3 gF (FDIM / BN, MROWS / BM);
    dim3 gV (VDIM / BN, MROWS / BM);
    dim3 gAtt(SDIM / TQ, HNUM, BNUM);
    const int gLN = MROWS / 8;   // warp per row, 8 rows per block

    for (int l = 0; l < LNUM; l++) {
        size_t oDD = (size_t)l * DDIM * DDIM;
        size_t oDF = (size_t)l * DDIM * FDIM;

        ln_kernel<<<gLN, 256>>>(x, ln1g + l * DDIM, ln1b + l * DDIM, hh, hl);

        gemm_as<false, false, true><<<gQKV, 256, SMEM_MM>>>(
            hh, hl, wqkvh + oDD, wqkvl + oDD, WZ,
            bq + l * DDIM, bk + l * DDIM, bv + l * DDIM,
            nullptr, CZ, qkvh, qkvl, MROWS, DDIM, DDIM);

        attn_mma<<<gAtt, 256, AT_SMEM>>>(qh, ql_, kh, kl, vh, vl, atth, attl);

        gemm_as<false, true, false><<<gD, 256, SMEM_MM>>>(
            atth, attl, woh + oDD, wol + oDD, 0,
            bo + l * DDIM, nullptr, nullptr,
            x, 0, nullptr, nullptr, MROWS, DDIM, DDIM);

        ln_kernel<<<gLN, 256>>>(x, ln2g + l * DDIM, ln2b + l * DDIM, hh, hl);

        gemm_as<true, false, true><<<gF, 256, SMEM_MM>>>(
            hh, hl, w1h + oDF, w1l + oDF, 0,
            b1 + l * FDIM, nullptr, nullptr,
            nullptr, 0, midh, midl, MROWS, FDIM, DDIM);

        gemm_as<false, true, false><<<gD, 256, SMEM_MM>>>(
            midh, midl, w2h + oDF, w2l + oDF, 0,
            b2 + l * DDIM, nullptr, nullptr,
            x, 0, nullptr, nullptr, MROWS, DDIM, FDIM);
    }

    ln_kernel<<<gLN, 256>>>(x, lnfg, lnfb, hh, hl);
    gemm_as<false, false, false><<<gV, 256, SMEM_MM>>>(
        hh, hl, wouth, woutl, 0,
        bout, nullptr, nullptr,
        out, 0, nullptr, nullptr, MROWS, VDIM, DDIM);
}